// round 10
// baseline (speedup 1.0000x reference)
#include <cuda_runtime.h>
#include <cuda_bf16.h>
#include <cstdint>

// Problem constants
#define B_SZ   4096
#define DIN    768
#define DOUT   512
#define Q_SZ   64
#define H1_SZ  32
#define H2_SZ  64
#define EPS    1e-5f

// GEMM1 split-K: K' = 3 * DIN, split across 2 CTAs in z
#define KSPLIT (3 * DIN)          // 2304
#define KC     64
#define NCHH   (KSPLIT / KC / 2)  // 18 chunks per K-half
#define GS     3                  // pipeline stages
#define TILEB  16384              // one 128x64 bf16 tile
#define STAGEB (2 * TILEB)

// ---------------------------------------------------------------------------
// Static device scratch
// ---------------------------------------------------------------------------
__device__ __align__(256) float          g_xp[2][B_SZ * DOUT];          // 16 MB partials
__device__ __align__(256) __nv_bfloat16  g_A[B_SZ * KSPLIT];            // 18.9 MB
__device__ __align__(256) __nv_bfloat16  g_Bt[DOUT * KSPLIT];           // 2.36 MB

// ---------------------------------------------------------------------------
// Helpers
// ---------------------------------------------------------------------------
__device__ __forceinline__ uint32_t smem_u32(const void* p) {
    uint32_t a;
    asm("{ .reg .u64 t; cvta.to.shared.u64 t, %1; cvt.u32.u64 %0, t; }"
        : "=r"(a) : "l"(p));
    return a;
}
__device__ __forceinline__ uint32_t swz(uint32_t off) {
    return off ^ ((off >> 3) & 0x70);
}
__device__ __forceinline__ void cpasync16(uint32_t dst, const void* src) {
    asm volatile("cp.async.cg.shared.global [%0], [%1], 16;"
                 :: "r"(dst), "l"(src) : "memory");
}
__device__ __forceinline__ void ldsm_x4(uint32_t* r, uint32_t addr) {
    asm volatile("ldmatrix.sync.aligned.m8n8.x4.shared.b16 {%0,%1,%2,%3}, [%4];"
                 : "=r"(r[0]), "=r"(r[1]), "=r"(r[2]), "=r"(r[3]) : "r"(addr));
}
__device__ __forceinline__ void mma16816(float* d, const uint32_t* a, const uint32_t* b) {
    asm volatile(
        "mma.sync.aligned.m16n8k16.row.col.f32.bf16.bf16.f32 "
        "{%0,%1,%2,%3}, {%4,%5,%6,%7}, {%8,%9}, {%0,%1,%2,%3};"
        : "+f"(d[0]), "+f"(d[1]), "+f"(d[2]), "+f"(d[3])
        : "r"(a[0]), "r"(a[1]), "r"(a[2]), "r"(a[3]), "r"(b[0]), "r"(b[1]));
}

// ---- packed f32x2 ----
__device__ __forceinline__ uint64_t pk2(float x, float y) {
    uint64_t r; asm("mov.b64 %0,{%1,%2};" : "=l"(r) : "f"(x), "f"(y)); return r;
}
__device__ __forceinline__ void upk2(uint64_t v, float& x, float& y) {
    asm("mov.b64 {%0,%1},%2;" : "=f"(x), "=f"(y) : "l"(v));
}
__device__ __forceinline__ uint64_t fma2(uint64_t a, uint64_t b, uint64_t c) {
    uint64_t d; asm("fma.rn.f32x2 %0,%1,%2,%3;" : "=l"(d) : "l"(a), "l"(b), "l"(c));
    return d;
}
__device__ __forceinline__ uint64_t add2(uint64_t a, uint64_t b) {
    uint64_t d; asm("add.rn.f32x2 %0,%1,%2;" : "=l"(d) : "l"(a), "l"(b));
    return d;
}
__device__ __forceinline__ uint64_t abs2(uint64_t a) {
    uint64_t d; asm("and.b64 %0,%1,0x7FFFFFFF7FFFFFFF;" : "=l"(d) : "l"(a));
    return d;
}

// ---------------------------------------------------------------------------
// Conversions (fp32 -> bf16 hi/lo, 3-term fold into K)
// ---------------------------------------------------------------------------
__global__ void __launch_bounds__(256)
conv_x(const float* __restrict__ x, __nv_bfloat16* __restrict__ A)
{
    const int row = blockIdx.x;
    const float* xr = x + (long)row * DIN;
    __nv_bfloat16* Ar = A + (long)row * KSPLIT;
    #pragma unroll
    for (int i = 0; i < 3; i++) {
        const int k = threadIdx.x + i * 256;
        const float v = xr[k];
        const __nv_bfloat16 hi = __float2bfloat16(v);
        const __nv_bfloat16 lo = __float2bfloat16(v - __bfloat162float(hi));
        Ar[k]            = hi;
        Ar[k + DIN]      = hi;
        Ar[k + 2 * DIN]  = lo;
    }
}

__global__ void __launch_bounds__(256)
conv_w(const float* __restrict__ wp, __nv_bfloat16* __restrict__ Bt)
{
    __shared__ float t[32][33];
    const int k0 = blockIdx.x * 32, n0 = blockIdx.y * 32;
    const int tx = threadIdx.x & 31;
    const int ty = threadIdx.x >> 5;
    #pragma unroll
    for (int dy = 0; dy < 32; dy += 8)
        t[ty + dy][tx] = wp[(long)(k0 + ty + dy) * DOUT + n0 + tx];
    __syncthreads();
    #pragma unroll
    for (int dy = 0; dy < 32; dy += 8) {
        const int n = n0 + ty + dy, k = k0 + tx;
        const float v = t[tx][ty + dy];
        const __nv_bfloat16 hi = __float2bfloat16(v);
        const __nv_bfloat16 lo = __float2bfloat16(v - __bfloat162float(hi));
        __nv_bfloat16* Br = Bt + (long)n * KSPLIT;
        Br[k]           = hi;
        Br[k + DIN]     = lo;
        Br[k + 2 * DIN] = hi;
    }
}

// ---------------------------------------------------------------------------
// GEMM1, split-K=2 (unchanged from R9, measured improvement)
// ---------------------------------------------------------------------------
__global__ void __launch_bounds__(256, 2)
gemm_tc(const __nv_bfloat16* __restrict__ Ag, const __nv_bfloat16* __restrict__ Bg,
        float* __restrict__ Cbase)
{
    extern __shared__ char dynsmem[];

    const int tid  = threadIdx.x;
    const int warp = tid >> 5, lane = tid & 31;
    const int wm = warp >> 2;
    const int wn = warp & 3;
    const int bn = blockIdx.x, bm = blockIdx.y, kz = blockIdx.z;

    const uint32_t abase = (smem_u32(dynsmem) + 1023u) & ~1023u;

    const __nv_bfloat16* Atile = Ag + (long)(bm * 128) * KSPLIT;
    const __nv_bfloat16* Btile = Bg + (long)(bn * 128) * KSPLIT;
    float* C = Cbase + (long)kz * (B_SZ * DOUT);
    const int kbase = kz * (NCHH * KC);

    auto load_chunk = [&](int c, int s) {
        const uint32_t sa = abase + s * STAGEB;
        const uint32_t sb = sa + TILEB;
        const int koff = kbase + c * KC;
        #pragma unroll
        for (int it = 0; it < 4; it++) {
            const int idx = it * 256 + tid;
            const int row = idx >> 3;
            const int c16 = idx & 7;
            const uint32_t soff = swz(row * 128 + c16 * 16);
            cpasync16(sa + soff, Atile + (long)row * KSPLIT + koff + c16 * 8);
            cpasync16(sb + soff, Btile + (long)row * KSPLIT + koff + c16 * 8);
        }
        asm volatile("cp.async.commit_group;" ::: "memory");
    };

    float acc[4][4][4];
    #pragma unroll
    for (int mt = 0; mt < 4; mt++)
        #pragma unroll
        for (int nt = 0; nt < 4; nt++)
            #pragma unroll
            for (int j = 0; j < 4; j++) acc[mt][nt][j] = 0.f;

    const uint32_t a_row = wm * 64 + (lane & 15);
    const uint32_t a_seg = (lane >> 4) * 16;
    const uint32_t b_row4 = wn * 32 + (lane & 7) + ((lane >> 4) << 3);
    const uint32_t b_seg4 = ((lane >> 3) & 1) * 16;

    load_chunk(0, 0);
    load_chunk(1, 1);

    int s_cons = 0, s_load = 2;
    for (int c = 0; c < NCHH; c++) {
        asm volatile("cp.async.wait_group %0;" :: "n"(GS - 2) : "memory");
        __syncthreads();

        const int nl = c + GS - 1;
        if (nl < NCHH) load_chunk(nl, s_load);
        if (++s_load == GS) s_load = 0;

        const uint32_t sa = abase + s_cons * STAGEB;
        const uint32_t sb = sa + TILEB;
        if (++s_cons == GS) s_cons = 0;

        #pragma unroll
        for (int ks = 0; ks < 4; ks++) {
            uint32_t bf[2][4];
            ldsm_x4(bf[0], sb + swz((b_row4)      * 128 + ks * 32 + b_seg4));
            ldsm_x4(bf[1], sb + swz((b_row4 + 16) * 128 + ks * 32 + b_seg4));
            #pragma unroll
            for (int mt = 0; mt < 4; mt++) {
                uint32_t af[4];
                ldsm_x4(af, sa + swz((a_row + mt * 16) * 128 + ks * 32 + a_seg));
                mma16816(acc[mt][0], af, &bf[0][0]);
                mma16816(acc[mt][1], af, &bf[0][2]);
                mma16816(acc[mt][2], af, &bf[1][0]);
                mma16816(acc[mt][3], af, &bf[1][2]);
            }
        }
    }

    const int g  = lane >> 2;
    const int tg = lane & 3;
    #pragma unroll
    for (int mt = 0; mt < 4; mt++) {
        const int m = bm * 128 + wm * 64 + mt * 16 + g;
        #pragma unroll
        for (int nt = 0; nt < 4; nt++) {
            const int n = bn * 128 + wn * 32 + nt * 8 + 2 * tg;
            float2 v0, v1;
            v0.x = acc[mt][nt][0];  v0.y = acc[mt][nt][1];
            v1.x = acc[mt][nt][2];  v1.y = acc[mt][nt][3];
            *(float2*)(C + (long)m * DOUT + n)       = v0;
            *(float2*)(C + (long)(m + 8) * DOUT + n) = v1;
        }
    }
}

// ---------------------------------------------------------------------------
// Kernel 2: ROWS=8, 512 threads, grid=512. 16 warps/CTA halves each stage's
// serial path; 2 CTAs/SM co-resident (regs ~48, smem ~23KB) -> occ ~50%.
// ---------------------------------------------------------------------------
#define ROWS  8
#define KTHR  512

__global__ void __launch_bounds__(KTHR)
kan_fused(const float* __restrict__ xp0, const float* __restrict__ xp1,
          const float* __restrict__ bp,
          const float* __restrict__ wi1, const float* __restrict__ bi1,
          const float* __restrict__ wi2, const float* __restrict__ bi2,
          const float* __restrict__ wo1, const float* __restrict__ bo1,
          const float* __restrict__ wo2, const float* __restrict__ bo2,
          const float* __restrict__ gamma, const float* __restrict__ beta,
          float* __restrict__ out)
{
    __shared__ float rows[ROWS][DOUT];       // 16 KB
    __shared__ float Ssh[2][ROWS][H1_SZ];    // 2 KB  (two half-sums)
    __shared__ float ush[ROWS][Q_SZ];        // 2 KB
    __shared__ float GshT[H2_SZ][ROWS];      // 2 KB  [h2][r], float4-aligned
    __shared__ float red[ROWS][16][2];       // 1 KB
    __shared__ float muS[ROWS], invS[ROWS];

    const int tid  = threadIdx.x;
    const int warp = tid >> 5;
    const int lane = tid & 31;
    const long base = (long)blockIdx.x * ROWS * DOUT;

    // Load 8 rows: xp0 + xp1 + bias  (1024 float4, 2 iters of 512 thr)
    {
        const float4* s0 = (const float4*)(xp0 + base);
        const float4* s1 = (const float4*)(xp1 + base);
        const float4* bb = (const float4*)bp;
        float4* dst = (float4*)(&rows[0][0]);
        #pragma unroll
        for (int i = 0; i < 2; i++) {
            const int j = tid + i * KTHR;
            const float4 a = s0[j];
            const float4 b = s1[j];
            const float4 c = bb[j & 127];
            float4 o;
            o.x = a.x + b.x + c.x;
            o.y = a.y + b.y + c.y;
            o.z = a.z + b.z + c.z;
            o.w = a.w + b.w + c.w;
            dst[j] = o;
        }
    }
    __syncthreads();

    // Stage B: warp -> (row = w>>1, half = w&1); half covers 256 d's; lane = h.
    // Half contribution: 0.5*(w*Vh + 256b + sum_h |v*w+b|); halves sum to S.
    {
        const int r = warp >> 1, half = warp & 1;
        const float4* rv = (const float4*)(&rows[r][0]) + half * 64;

        uint64_t vp = pk2(0.f, 0.f);
        #pragma unroll
        for (int i = 0; i < 2; i++) {
            const float4 v = rv[lane + i * 32];
            vp = add2(vp, pk2(v.x, v.y));
            vp = add2(vp, pk2(v.z, v.w));
        }
        float t0, t1; upk2(vp, t0, t1);
        float vs = t0 + t1;
        #pragma unroll
        for (int off = 16; off > 0; off >>= 1)
            vs += __shfl_xor_sync(0xffffffffu, vs, off);

        const float w1 = wi1[lane];
        const float b1 = bi1[lane];
        const uint64_t w11 = pk2(w1, w1);
        const uint64_t b11 = pk2(b1, b1);
        uint64_t s01 = pk2(0.f, 0.f), s23 = pk2(0.f, 0.f);
        #pragma unroll 4
        for (int d4 = 0; d4 < 64; d4++) {
            const float4 v = rv[d4];
            s01 = add2(s01, abs2(fma2(pk2(v.x, v.y), w11, b11)));
            s23 = add2(s23, abs2(fma2(pk2(v.z, v.w), w11, b11)));
        }
        float a0, a1, a2, a3;
        upk2(s01, a0, a1); upk2(s23, a2, a3);
        const float sabs = (a0 + a1) + (a2 + a3);
        Ssh[half][r][lane] = 0.5f * (fmaf(w1, vs, 256.0f * b1) + sabs);
    }
    __syncthreads();

    // Stage C: one thread per (r, q). r uniform per pair of warps.
    {
        const int r = tid >> 6, q = tid & 63;
        float acc = (float)DOUT * bi2[q];
        #pragma unroll
        for (int h = 0; h < H1_SZ; h++)
            acc = fmaf(Ssh[0][r][h] + Ssh[1][r][h], wi2[h * Q_SZ + q], acc);
        ush[r][q] = acc;
    }
    __syncthreads();

    // Stage D: one thread per (r, h2); ush reads are uniform broadcasts.
    {
        const int r = tid >> 6, h2 = tid & 63;
        const float w = wo1[h2];
        const float b = bo1[h2];
        float g = 0.f;
        #pragma unroll
        for (int q = 0; q < Q_SZ; q++)
            g += fmaxf(fmaf(ush[r][q], w, b), 0.f);
        GshT[h2][r] = g;
    }
    __syncthreads();

    // Stage E: 1 col/thread (d = tid), 8 rows in 4 packed f32x2 accumulators.
    // Per h2: 1 coalesced LDG.32 + 2 broadcast LDS.128 + 4 FFMA2.
    const int d0 = tid;
    uint64_t acc2[4];
    #pragma unroll
    for (int p = 0; p < 4; p++) acc2[p] = pk2(0.f, 0.f);

    #pragma unroll 4
    for (int h2 = 0; h2 < H2_SZ; h2++) {
        const float w = wo2[h2 * DOUT + d0];
        const uint64_t ww = pk2(w, w);
        const float4* gp = (const float4*)(&GshT[h2][0]);
        const float4 g0 = gp[0], g1 = gp[1];
        acc2[0] = fma2(pk2(g0.x, g0.y), ww, acc2[0]);
        acc2[1] = fma2(pk2(g0.z, g0.w), ww, acc2[1]);
        acc2[2] = fma2(pk2(g1.x, g1.y), ww, acc2[2]);
        acc2[3] = fma2(pk2(g1.z, g1.w), ww, acc2[3]);
    }

    float ax[ROWS];
    {
        const float bb = (float)Q_SZ * bo2[d0];
        const uint64_t bb2 = pk2(bb, bb);
        #pragma unroll
        for (int p = 0; p < 4; p++) {
            acc2[p] = add2(acc2[p], bb2);
            upk2(acc2[p], ax[2 * p], ax[2 * p + 1]);
        }
    }

    // LayerNorm: per-row reduce over 512 cols = 32 lanes x 16 warps.
    #pragma unroll
    for (int r = 0; r < ROWS; r++) {
        float ps = ax[r];
        float pq = ax[r] * ax[r];
        #pragma unroll
        for (int off = 16; off > 0; off >>= 1) {
            ps += __shfl_xor_sync(0xffffffffu, ps, off);
            pq += __shfl_xor_sync(0xffffffffu, pq, off);
        }
        if (lane == 0) { red[r][warp][0] = ps; red[r][warp][1] = pq; }
    }
    __syncthreads();

    if (tid < ROWS) {
        float s = 0.f, q2 = 0.f;
        #pragma unroll
        for (int w = 0; w < 16; w++) { s += red[tid][w][0]; q2 += red[tid][w][1]; }
        const float mu  = s * (1.f / (float)DOUT);
        const float var = q2 * (1.f / (float)DOUT) - mu * mu;
        muS[tid]  = mu;
        invS[tid] = rsqrtf(var + EPS);
    }
    __syncthreads();

    const float gm = gamma[d0];
    const float bt = beta[d0];
    #pragma unroll
    for (int r = 0; r < ROWS; r++) {
        out[base + (long)r * DOUT + d0] =
            (ax[r] - muS[r]) * invS[r] * gm + bt;
    }
}

// ---------------------------------------------------------------------------
// Launch
// ---------------------------------------------------------------------------
extern "C" void kernel_launch(void* const* d_in, const int* in_sizes, int n_in,
                              void* d_out, int out_size)
{
    const float* x     = (const float*)d_in[0];
    const float* wp    = (const float*)d_in[1];
    const float* bp    = (const float*)d_in[2];
    const float* wi1   = (const float*)d_in[3];
    const float* bi1   = (const float*)d_in[4];
    const float* wi2   = (const float*)d_in[5];
    const float* bi2   = (const float*)d_in[6];
    const float* wo1   = (const float*)d_in[7];
    const float* bo1   = (const float*)d_in[8];
    const float* wo2   = (const float*)d_in[9];
    const float* bo2   = (const float*)d_in[10];
    const float* gamma = (const float*)d_in[11];
    const float* beta  = (const float*)d_in[12];
    float* out = (float*)d_out;

    float* xp;             cudaGetSymbolAddress((void**)&xp, g_xp);
    __nv_bfloat16* Ab;     cudaGetSymbolAddress((void**)&Ab, g_A);
    __nv_bfloat16* Bb;     cudaGetSymbolAddress((void**)&Bb, g_Bt);

    conv_x<<<B_SZ, 256>>>(x, Ab);
    conv_w<<<dim3(DIN / 32, DOUT / 32), 256>>>(wp, Bb);

    const int dyn = GS * STAGEB + 1024;   // ~97 KB
    cudaFuncSetAttribute(gemm_tc, cudaFuncAttributeMaxDynamicSharedMemorySize, dyn);
    gemm_tc<<<dim3(DOUT / 128, B_SZ / 128, 2), 256, dyn>>>(Ab, Bb, xp);

    kan_fused<<<B_SZ / ROWS, KTHR>>>(xp, xp + (long)B_SZ * DOUT, bp,
                                     wi1, bi1, wi2, bi2,
                                     wo1, bo1, wo2, bo2, gamma, beta, out);
}

// round 11
// speedup vs baseline: 1.0745x; 1.0745x over previous
#include <cuda_runtime.h>
#include <cuda_bf16.h>
#include <cstdint>

// Problem constants
#define B_SZ   4096
#define DIN    768
#define DOUT   512
#define Q_SZ   64
#define H1_SZ  32
#define H2_SZ  64
#define EPS    1e-5f

// GEMM1 split-K: effective K' = 3 * DIN (hi@hi + hi@lo + lo@hi),
// A stored DEDUPED as [x_hi | x_lo] (KA = 2*DIN); chunk remap re-reads hi.
#define KSPLIT (3 * DIN)          // 2304 (B operand extent)
#define KA     (2 * DIN)          // 1536 (A operand extent, deduped)
#define KC     64
#define NCHH   (KSPLIT / KC / 2)  // 18 chunks per K-half
#define GS     3                  // pipeline stages
#define TILEB  16384              // one 128x64 bf16 tile
#define STAGEB (2 * TILEB)

// ---------------------------------------------------------------------------
// Static device scratch
// ---------------------------------------------------------------------------
__device__ __align__(256) float          g_xp[2][B_SZ * DOUT];          // 16 MB partials
__device__ __align__(256) __nv_bfloat16  g_A[B_SZ * KA];                // 12.6 MB
__device__ __align__(256) __nv_bfloat16  g_Bt[DOUT * KSPLIT];           // 2.36 MB

// ---------------------------------------------------------------------------
// Helpers
// ---------------------------------------------------------------------------
__device__ __forceinline__ uint32_t smem_u32(const void* p) {
    uint32_t a;
    asm("{ .reg .u64 t; cvta.to.shared.u64 t, %1; cvt.u32.u64 %0, t; }"
        : "=r"(a) : "l"(p));
    return a;
}
__device__ __forceinline__ uint32_t swz(uint32_t off) {
    return off ^ ((off >> 3) & 0x70);
}
__device__ __forceinline__ void cpasync16(uint32_t dst, const void* src) {
    asm volatile("cp.async.cg.shared.global [%0], [%1], 16;"
                 :: "r"(dst), "l"(src) : "memory");
}
__device__ __forceinline__ void ldsm_x4(uint32_t* r, uint32_t addr) {
    asm volatile("ldmatrix.sync.aligned.m8n8.x4.shared.b16 {%0,%1,%2,%3}, [%4];"
                 : "=r"(r[0]), "=r"(r[1]), "=r"(r[2]), "=r"(r[3]) : "r"(addr));
}
__device__ __forceinline__ void mma16816(float* d, const uint32_t* a, const uint32_t* b) {
    asm volatile(
        "mma.sync.aligned.m16n8k16.row.col.f32.bf16.bf16.f32 "
        "{%0,%1,%2,%3}, {%4,%5,%6,%7}, {%8,%9}, {%0,%1,%2,%3};"
        : "+f"(d[0]), "+f"(d[1]), "+f"(d[2]), "+f"(d[3])
        : "r"(a[0]), "r"(a[1]), "r"(a[2]), "r"(a[3]), "r"(b[0]), "r"(b[1]));
}

// ---- packed f32x2 ----
__device__ __forceinline__ uint64_t pk2(float x, float y) {
    uint64_t r; asm("mov.b64 %0,{%1,%2};" : "=l"(r) : "f"(x), "f"(y)); return r;
}
__device__ __forceinline__ void upk2(uint64_t v, float& x, float& y) {
    asm("mov.b64 {%0,%1},%2;" : "=f"(x), "=f"(y) : "l"(v));
}
__device__ __forceinline__ uint64_t fma2(uint64_t a, uint64_t b, uint64_t c) {
    uint64_t d; asm("fma.rn.f32x2 %0,%1,%2,%3;" : "=l"(d) : "l"(a), "l"(b), "l"(c));
    return d;
}
__device__ __forceinline__ uint64_t add2(uint64_t a, uint64_t b) {
    uint64_t d; asm("add.rn.f32x2 %0,%1,%2;" : "=l"(d) : "l"(a), "l"(b));
    return d;
}
__device__ __forceinline__ uint64_t abs2(uint64_t a) {
    uint64_t d; asm("and.b64 %0,%1,0x7FFFFFFF7FFFFFFF;" : "=l"(d) : "l"(a));
    return d;
}

// ---------------------------------------------------------------------------
// Conversions (fp32 -> bf16 hi/lo). A deduped: [x_hi (768) | x_lo (768)].
// B (w^T) keeps 3 regions: [w_hi ; w_lo ; w_hi].
// ---------------------------------------------------------------------------
__global__ void __launch_bounds__(256)
conv_x(const float* __restrict__ x, __nv_bfloat16* __restrict__ A)
{
    const int row = blockIdx.x;
    const float* xr = x + (long)row * DIN;
    __nv_bfloat16* Ar = A + (long)row * KA;
    #pragma unroll
    for (int i = 0; i < 3; i++) {
        const int k = threadIdx.x + i * 256;
        const float v = xr[k];
        const __nv_bfloat16 hi = __float2bfloat16(v);
        const __nv_bfloat16 lo = __float2bfloat16(v - __bfloat162float(hi));
        Ar[k]       = hi;
        Ar[k + DIN] = lo;
    }
}

__global__ void __launch_bounds__(256)
conv_w(const float* __restrict__ wp, __nv_bfloat16* __restrict__ Bt)
{
    __shared__ float t[32][33];
    const int k0 = blockIdx.x * 32, n0 = blockIdx.y * 32;
    const int tx = threadIdx.x & 31;
    const int ty = threadIdx.x >> 5;
    #pragma unroll
    for (int dy = 0; dy < 32; dy += 8)
        t[ty + dy][tx] = wp[(long)(k0 + ty + dy) * DOUT + n0 + tx];
    __syncthreads();
    #pragma unroll
    for (int dy = 0; dy < 32; dy += 8) {
        const int n = n0 + ty + dy, k = k0 + tx;
        const float v = t[tx][ty + dy];
        const __nv_bfloat16 hi = __float2bfloat16(v);
        const __nv_bfloat16 lo = __float2bfloat16(v - __bfloat162float(hi));
        __nv_bfloat16* Br = Bt + (long)n * KSPLIT;
        Br[k]           = hi;
        Br[k + DIN]     = lo;
        Br[k + 2 * DIN] = hi;
    }
}

// ---------------------------------------------------------------------------
// GEMM1, split-K=2. A chunk offsets remapped onto the deduped [hi|lo] buffer:
//   global chunk gc in [0,36): gc<12 -> hi col gc*64; 12<=gc<24 -> hi col
//   (gc-12)*64 (re-read, L2-resident); gc>=24 -> lo col 768+(gc-24)*64.
// ---------------------------------------------------------------------------
__global__ void __launch_bounds__(256, 2)
gemm_tc(const __nv_bfloat16* __restrict__ Ag, const __nv_bfloat16* __restrict__ Bg,
        float* __restrict__ Cbase)
{
    extern __shared__ char dynsmem[];

    const int tid  = threadIdx.x;
    const int warp = tid >> 5, lane = tid & 31;
    const int wm = warp >> 2;
    const int wn = warp & 3;
    const int bn = blockIdx.x, bm = blockIdx.y, kz = blockIdx.z;

    const uint32_t abase = (smem_u32(dynsmem) + 1023u) & ~1023u;

    const __nv_bfloat16* Atile = Ag + (long)(bm * 128) * KA;
    const __nv_bfloat16* Btile = Bg + (long)(bn * 128) * KSPLIT;
    float* C = Cbase + (long)kz * (B_SZ * DOUT);
    const int gc0 = kz * NCHH;

    auto load_chunk = [&](int c, int s) {
        const uint32_t sa = abase + s * STAGEB;
        const uint32_t sb = sa + TILEB;
        const int gc = gc0 + c;
        const int aoff = (gc < 12) ? gc * 64
                       : (gc < 24) ? (gc - 12) * 64
                                   : DIN + (gc - 24) * 64;
        const int boff = gc * 64;
        #pragma unroll
        for (int it = 0; it < 4; it++) {
            const int idx = it * 256 + tid;
            const int row = idx >> 3;
            const int c16 = idx & 7;
            const uint32_t soff = swz(row * 128 + c16 * 16);
            cpasync16(sa + soff, Atile + (long)row * KA     + aoff + c16 * 8);
            cpasync16(sb + soff, Btile + (long)row * KSPLIT + boff + c16 * 8);
        }
        asm volatile("cp.async.commit_group;" ::: "memory");
    };

    float acc[4][4][4];
    #pragma unroll
    for (int mt = 0; mt < 4; mt++)
        #pragma unroll
        for (int nt = 0; nt < 4; nt++)
            #pragma unroll
            for (int j = 0; j < 4; j++) acc[mt][nt][j] = 0.f;

    const uint32_t a_row = wm * 64 + (lane & 15);
    const uint32_t a_seg = (lane >> 4) * 16;
    const uint32_t b_row4 = wn * 32 + (lane & 7) + ((lane >> 4) << 3);
    const uint32_t b_seg4 = ((lane >> 3) & 1) * 16;

    load_chunk(0, 0);
    load_chunk(1, 1);

    int s_cons = 0, s_load = 2;
    for (int c = 0; c < NCHH; c++) {
        asm volatile("cp.async.wait_group %0;" :: "n"(GS - 2) : "memory");
        __syncthreads();

        const int nl = c + GS - 1;
        if (nl < NCHH) load_chunk(nl, s_load);
        if (++s_load == GS) s_load = 0;

        const uint32_t sa = abase + s_cons * STAGEB;
        const uint32_t sb = sa + TILEB;
        if (++s_cons == GS) s_cons = 0;

        #pragma unroll
        for (int ks = 0; ks < 4; ks++) {
            uint32_t bf[2][4];
            ldsm_x4(bf[0], sb + swz((b_row4)      * 128 + ks * 32 + b_seg4));
            ldsm_x4(bf[1], sb + swz((b_row4 + 16) * 128 + ks * 32 + b_seg4));
            #pragma unroll
            for (int mt = 0; mt < 4; mt++) {
                uint32_t af[4];
                ldsm_x4(af, sa + swz((a_row + mt * 16) * 128 + ks * 32 + a_seg));
                mma16816(acc[mt][0], af, &bf[0][0]);
                mma16816(acc[mt][1], af, &bf[0][2]);
                mma16816(acc[mt][2], af, &bf[1][0]);
                mma16816(acc[mt][3], af, &bf[1][2]);
            }
        }
    }

    const int g  = lane >> 2;
    const int tg = lane & 3;
    #pragma unroll
    for (int mt = 0; mt < 4; mt++) {
        const int m = bm * 128 + wm * 64 + mt * 16 + g;
        #pragma unroll
        for (int nt = 0; nt < 4; nt++) {
            const int n = bn * 128 + wn * 32 + nt * 8 + 2 * tg;
            float2 v0, v1;
            v0.x = acc[mt][nt][0];  v0.y = acc[mt][nt][1];
            v1.x = acc[mt][nt][2];  v1.y = acc[mt][nt][3];
            *(float2*)(C + (long)m * DOUT + n)       = v0;
            *(float2*)(C + (long)(m + 8) * DOUT + n) = v1;
        }
    }
}

// ---------------------------------------------------------------------------
// Kernel 2: R7-exact structure (best measured): ROWS=8, 256 threads.
// (p0+p1+bias) -> S(abs identity, f32x2) -> u -> G^T -> E(f32x2) -> LayerNorm
// ---------------------------------------------------------------------------
#define ROWS 8

__global__ void __launch_bounds__(256)
kan_fused(const float* __restrict__ xp0, const float* __restrict__ xp1,
          const float* __restrict__ bp,
          const float* __restrict__ wi1, const float* __restrict__ bi1,
          const float* __restrict__ wi2, const float* __restrict__ bi2,
          const float* __restrict__ wo1, const float* __restrict__ bo1,
          const float* __restrict__ wo2, const float* __restrict__ bo2,
          const float* __restrict__ gamma, const float* __restrict__ beta,
          float* __restrict__ out)
{
    __shared__ float rows[ROWS][DOUT];
    __shared__ float Ssh[ROWS][H1_SZ];
    __shared__ float ush[ROWS][Q_SZ];
    __shared__ float GshT[H2_SZ][ROWS];     // transposed: [h2][r]
    __shared__ float red[ROWS][8][2];

    const int tid  = threadIdx.x;
    const int warp = tid >> 5;
    const int lane = tid & 31;
    const long base = (long)blockIdx.x * ROWS * DOUT;

    // Load 8 rows: xp0 + xp1 + bias
    {
        const float4* s0 = (const float4*)(xp0 + base);
        const float4* s1 = (const float4*)(xp1 + base);
        const float4* bb = (const float4*)bp;
        float4* dst = (float4*)(&rows[0][0]);
        #pragma unroll
        for (int i = 0; i < 4; i++) {
            const int j = tid + i * 256;
            const float4 a = s0[j];
            const float4 b = s1[j];
            const float4 c = bb[j & 127];
            float4 o;
            o.x = a.x + b.x + c.x;
            o.y = a.y + b.y + c.y;
            o.z = a.z + b.z + c.z;
            o.w = a.w + b.w + c.w;
            dst[j] = o;
        }
    }
    __syncthreads();

    // Stage B: S = 0.5*(w*V + 512*b + sum|v*w+b|)   (packed f32x2)
    {
        const float4* rv = (const float4*)(&rows[warp][0]);

        uint64_t vp = pk2(0.f, 0.f);
        #pragma unroll
        for (int i = 0; i < 4; i++) {
            const float4 v = rv[lane + i * 32];
            vp = add2(vp, pk2(v.x, v.y));
            vp = add2(vp, pk2(v.z, v.w));
        }
        float va, vb; upk2(vp, va, vb);
        float vs = va + vb;
        #pragma unroll
        for (int off = 16; off > 0; off >>= 1)
            vs += __shfl_xor_sync(0xffffffffu, vs, off);

        const float w1 = wi1[lane];
        const float b1 = bi1[lane];
        const uint64_t w11 = pk2(w1, w1);
        const uint64_t b11 = pk2(b1, b1);
        uint64_t s01 = pk2(0.f, 0.f), s23 = pk2(0.f, 0.f);
        #pragma unroll 4
        for (int d4 = 0; d4 < DOUT / 4; d4++) {
            const float4 v = rv[d4];
            s01 = add2(s01, abs2(fma2(pk2(v.x, v.y), w11, b11)));
            s23 = add2(s23, abs2(fma2(pk2(v.z, v.w), w11, b11)));
        }
        float a0, a1, a2, a3;
        upk2(s01, a0, a1); upk2(s23, a2, a3);
        const float sabs = (a0 + a1) + (a2 + a3);
        Ssh[warp][lane] = 0.5f * (fmaf(w1, vs, (float)DOUT * b1) + sabs);
    }
    __syncthreads();

    // Stage C: u[r][q]
    #pragma unroll
    for (int it = 0; it < 2; it++) {
        const int idx = tid + it * 256;
        const int r = idx >> 6, q = idx & 63;
        float acc = (float)DOUT * bi2[q];
        #pragma unroll
        for (int h = 0; h < H1_SZ; h++)
            acc = fmaf(Ssh[r][h], wi2[h * Q_SZ + q], acc);
        ush[r][q] = acc;
    }
    __syncthreads();

    // Stage D: G[r][h2] -> stored transposed
    #pragma unroll
    for (int it = 0; it < 2; it++) {
        const int idx = tid + it * 256;
        const int r = idx >> 6, h2 = idx & 63;
        const float w = wo1[h2];
        const float b = bo1[h2];
        float g = 0.f;
        #pragma unroll
        for (int q = 0; q < Q_SZ; q++)
            g += fmaxf(fmaf(ush[r][q], w, b), 0.f);
        GshT[h2][r] = g;
    }
    __syncthreads();

    // Stage E (packed f32x2): rows packed in pairs from float4 broadcasts.
    const int d0 = tid * 2;
    uint64_t acc2[8];
    #pragma unroll
    for (int j = 0; j < 8; j++) acc2[j] = pk2(0.f, 0.f);

    #pragma unroll 4
    for (int h2 = 0; h2 < H2_SZ; h2++) {
        const float2 w = *(const float2*)(wo2 + h2 * DOUT + d0);   // LDG.64
        const uint64_t wx = pk2(w.x, w.x);
        const uint64_t wy = pk2(w.y, w.y);
        const float4 ga = *(const float4*)(&GshT[h2][0]);          // rows 0-3 bcast
        const float4 gb = *(const float4*)(&GshT[h2][4]);          // rows 4-7 bcast
        const uint64_t g01 = pk2(ga.x, ga.y);
        const uint64_t g23 = pk2(ga.z, ga.w);
        const uint64_t g45 = pk2(gb.x, gb.y);
        const uint64_t g67 = pk2(gb.z, gb.w);
        acc2[0] = fma2(g01, wx, acc2[0]);
        acc2[1] = fma2(g23, wx, acc2[1]);
        acc2[2] = fma2(g45, wx, acc2[2]);
        acc2[3] = fma2(g67, wx, acc2[3]);
        acc2[4] = fma2(g01, wy, acc2[4]);
        acc2[5] = fma2(g23, wy, acc2[5]);
        acc2[6] = fma2(g45, wy, acc2[6]);
        acc2[7] = fma2(g67, wy, acc2[7]);
    }

    float ax[ROWS], ay[ROWS];
    {
        const float2 bo = *(const float2*)(bo2 + d0);
        const uint64_t bbx = pk2((float)Q_SZ * bo.x, (float)Q_SZ * bo.x);
        const uint64_t bby = pk2((float)Q_SZ * bo.y, (float)Q_SZ * bo.y);
        #pragma unroll
        for (int p = 0; p < 4; p++) {
            acc2[p]     = add2(acc2[p], bbx);
            acc2[4 + p] = add2(acc2[4 + p], bby);
            upk2(acc2[p],     ax[2 * p], ax[2 * p + 1]);
            upk2(acc2[4 + p], ay[2 * p], ay[2 * p + 1]);
        }
    }

    // LayerNorm reductions
    #pragma unroll
    for (int r = 0; r < ROWS; r++) {
        float ps = ax[r] + ay[r];
        float pq = ax[r] * ax[r] + ay[r] * ay[r];
        #pragma unroll
        for (int off = 16; off > 0; off >>= 1) {
            ps += __shfl_xor_sync(0xffffffffu, ps, off);
            pq += __shfl_xor_sync(0xffffffffu, pq, off);
        }
        if (lane == 0) { red[r][warp][0] = ps; red[r][warp][1] = pq; }
    }
    __syncthreads();

    const float2 gm = *(const float2*)(gamma + d0);
    const float2 bt = *(const float2*)(beta + d0);
    #pragma unroll
    for (int r = 0; r < ROWS; r++) {
        float s = 0.f, q2 = 0.f;
        #pragma unroll
        for (int w = 0; w < 8; w++) { s += red[r][w][0]; q2 += red[r][w][1]; }
        const float mu  = s * (1.f / (float)DOUT);
        const float var = q2 * (1.f / (float)DOUT) - mu * mu;
        const float inv = rsqrtf(var + EPS);
        float2 o;
        o.x = (ax[r] - mu) * inv * gm.x + bt.x;
        o.y = (ay[r] - mu) * inv * gm.y + bt.y;
        *(float2*)(out + base + (long)r * DOUT + d0) = o;
    }
}

// ---------------------------------------------------------------------------
// Launch
// ---------------------------------------------------------------------------
extern "C" void kernel_launch(void* const* d_in, const int* in_sizes, int n_in,
                              void* d_out, int out_size)
{
    const float* x     = (const float*)d_in[0];
    const float* wp    = (const float*)d_in[1];
    const float* bp    = (const float*)d_in[2];
    const float* wi1   = (const float*)d_in[3];
    const float* bi1   = (const float*)d_in[4];
    const float* wi2   = (const float*)d_in[5];
    const float* bi2   = (const float*)d_in[6];
    const float* wo1   = (const float*)d_in[7];
    const float* bo1   = (const float*)d_in[8];
    const float* wo2   = (const float*)d_in[9];
    const float* bo2   = (const float*)d_in[10];
    const float* gamma = (const float*)d_in[11];
    const float* beta  = (const float*)d_in[12];
    float* out = (float*)d_out;

    float* xp;             cudaGetSymbolAddress((void**)&xp, g_xp);
    __nv_bfloat16* Ab;     cudaGetSymbolAddress((void**)&Ab, g_A);
    __nv_bfloat16* Bb;     cudaGetSymbolAddress((void**)&Bb, g_Bt);

    conv_x<<<B_SZ, 256>>>(x, Ab);
    conv_w<<<dim3(DIN / 32, DOUT / 32), 256>>>(wp, Bb);

    const int dyn = GS * STAGEB + 1024;   // ~97 KB
    cudaFuncSetAttribute(gemm_tc, cudaFuncAttributeMaxDynamicSharedMemorySize, dyn);
    gemm_tc<<<dim3(DOUT / 128, B_SZ / 128, 2), 256, dyn>>>(Ab, Bb, xp);

    kan_fused<<<B_SZ / ROWS, 256>>>(xp, xp + (long)B_SZ * DOUT, bp,
                                    wi1, bi1, wi2, bi2,
                                    wo1, bo1, wo2, bo2, gamma, beta, out);
}